// round 12
// baseline (speedup 1.0000x reference)
#include <cuda_runtime.h>

#define BB   8
#define NPT  4096
#define DD   64
#define KP   1024
#define NNB  16
#define CC   128
#define CIN  67            // D + 3
#define MT   (BB*KP*NNB)   // 131072 rows
#define EPSBN 1e-5f

// ---------------- scratch ----------------
__device__ float g_h1[(size_t)MT*CC];
__device__ int   g_knn[MT];
__device__ float g_nxyz[BB*KP*3];
__device__ float g_W1T[CIN*CC];
__device__ float g_W2T[CC*CC];
__device__ float g_part[2*1024*CC];
__device__ float g_scale[2][CC];
__device__ float g_shift[2][CC];
__device__ float g_mx[(size_t)BB*KP*CC];
__device__ float g_mn[(size_t)BB*KP*CC];
__device__ unsigned g_prog[BB];            // FPS progress per batch
__device__ unsigned g_kdone[BB*128];       // kNN group-done flags (8 centers/group)

// ---------------- helpers ----------------
__device__ __forceinline__ unsigned redux_max_u32(unsigned v) {
    unsigned r; asm("redux.sync.max.u32 %0,%1,0xffffffff;" : "=r"(r) : "r"(v)); return r;
}
__device__ __forceinline__ unsigned redux_min_u32(unsigned v) {
    unsigned r; asm("redux.sync.min.u32 %0,%1,0xffffffff;" : "=r"(r) : "r"(v)); return r;
}
__device__ __forceinline__ void fma2(unsigned long long& d, unsigned long long a, unsigned long long b) {
    asm("fma.rn.f32x2 %0,%1,%2,%0;" : "+l"(d) : "l"(a), "l"(b));
}
__device__ __forceinline__ unsigned long long mul2(unsigned long long a, unsigned long long b) {
    unsigned long long r; asm("mul.rn.f32x2 %0,%1,%2;" : "=l"(r) : "l"(a), "l"(b)); return r;
}
__device__ __forceinline__ unsigned long long add2(unsigned long long a, unsigned long long b) {
    unsigned long long r; asm("add.rn.f32x2 %0,%1,%2;" : "=l"(r) : "l"(a), "l"(b)); return r;
}
__device__ __forceinline__ unsigned long long pk2(float lo, float hi) {
    unsigned long long r; asm("mov.b64 %0,{%1,%2};" : "=l"(r) : "f"(lo), "f"(hi)); return r;
}
__device__ __forceinline__ float2 u2f(unsigned long long v) {
    float2 f; asm("mov.b64 {%0,%1},%2;" : "=f"(f.x), "=f"(f.y) : "l"(v)); return f;
}

// ---------------- pre-kernels ----------------
__global__ void wt1_kernel(const float* __restrict__ W1) {
    if (threadIdx.x < BB) g_prog[threadIdx.x] = 0u;
    for (int i = threadIdx.x; i < BB*128; i += blockDim.x) g_kdone[i] = 0u;
    for (int idx = threadIdx.x; idx < CC*CIN; idx += blockDim.x) {
        int o = idx / CIN, c = idx - o*CIN;
        g_W1T[c*CC + o] = W1[idx];
    }
}
__global__ void wt2_kernel(const float* __restrict__ W2) {
    for (int idx = threadIdx.x; idx < CC*CC; idx += blockDim.x) {
        int o = idx >> 7, c = idx & 127;
        g_W2T[c*CC + o] = W2[idx];
    }
}

#define SAST 132   // scalar A tile stride (floats)

// ---------------- FPS body (blocks 0..7) ----------------
__device__ __forceinline__ void fps_body(float* fsm, const float* __restrict__ xyz,
                                         float* __restrict__ outx) {
    float4* sp = (float4*)fsm;
    unsigned* vslot = (unsigned*)(sp + NPT);
    unsigned* islot = vslot + 16;

    const int b    = blockIdx.x;
    const int st   = threadIdx.x;
    const int lane = st & 31, warp = st >> 5;
    const float* base = xyz + (size_t)b*NPT*3;

    float c[48];
    {
        const float4* s4 = (const float4*)(base + st*48);
#pragma unroll
        for (int q = 0; q < 12; q++) {
            float4 v = s4[q];
            c[4*q+0] = v.x; c[4*q+1] = v.y; c[4*q+2] = v.z; c[4*q+3] = v.w;
        }
    }
    unsigned long long pxp[8], pyp[8], pzp[8];
    float dist[16];
#pragma unroll
    for (int q = 0; q < 8; q++) {
        pxp[q] = pk2(c[6*q+0], c[6*q+3]);
        pyp[q] = pk2(c[6*q+1], c[6*q+4]);
        pzp[q] = pk2(c[6*q+2], c[6*q+5]);
        dist[2*q] = 1e10f; dist[2*q+1] = 1e10f;
    }
#pragma unroll
    for (int i = 0; i < 16; i++)
        sp[st*16 + i] = make_float4(c[3*i+0], c[3*i+1], c[3*i+2], 0.0f);
    __syncthreads();

    int far = 0;
    for (int t = 0; t < KP; t++) {
        float4 ctr = sp[far];
        if (st == 0) {
            int o = (b*KP + t)*3;
            g_nxyz[o+0] = ctr.x; g_nxyz[o+1] = ctr.y; g_nxyz[o+2] = ctr.z;
            if (outx) { outx[o+0] = ctr.x; outx[o+1] = ctr.y; outx[o+2] = ctr.z; }
            if ((t & 7) == 7) {
                __threadfence();
                *((volatile unsigned*)&g_prog[b]) = (unsigned)(t + 1);
            }
        }
        unsigned long long ncx = pk2(-ctr.x, -ctr.x), ncy = pk2(-ctr.y, -ctr.y), ncz = pk2(-ctr.z, -ctr.z);
#pragma unroll
        for (int q = 0; q < 8; q++) {
            unsigned long long dx = add2(pxp[q], ncx);
            unsigned long long dy = add2(pyp[q], ncy);
            unsigned long long dz = add2(pzp[q], ncz);
            unsigned long long dd = mul2(dx, dx);
            fma2(dd, dy, dy);
            fma2(dd, dz, dz);
            float2 e = u2f(dd);
            dist[2*q]   = fminf(dist[2*q],   e.x);
            dist[2*q+1] = fminf(dist[2*q+1], e.y);
        }
        float h[8];
#pragma unroll
        for (int i = 0; i < 8; i++) h[i] = fmaxf(dist[2*i], dist[2*i+1]);
        float h0 = fmaxf(fmaxf(h[0], h[1]), fmaxf(h[2], h[3]));
        float h1 = fmaxf(fmaxf(h[4], h[5]), fmaxf(h[6], h[7]));
        float tm = fmaxf(h0, h1);
        unsigned mb = redux_max_u32(__float_as_uint(tm));
        float m = __uint_as_float(mb);
        int li = 15;
#pragma unroll
        for (int i = 14; i >= 0; i--) li = (dist[i] == m) ? i : li;
        unsigned widx = redux_min_u32((__float_as_uint(tm) == mb)
                                      ? (unsigned)(st*16 + li) : 0xFFFFFFFFu);
        const int par = (t & 1) * 8;
        if (lane == 0) { vslot[par + warp] = mb; islot[par + warp] = widx; }
        __syncthreads();
        unsigned v  = vslot[par + (lane & 7)];
        unsigned iv = islot[par + (lane & 7)];
        unsigned m2 = redux_max_u32(v);
        far = (int)redux_min_u32((v == m2) ? iv : 0xFFFFFFFFu);
    }
    if (st == 0) {
        __threadfence();
        *((volatile unsigned*)&g_prog[b]) = (unsigned)KP;
    }
}

// ---------------- kNN body (blocks 8..135): contiguous groups, publish flags ----------------
__device__ __forceinline__ void knn_body(float* fsm, const float* __restrict__ xyz) {
    float* spx = fsm;
    float* spy = fsm + NPT;
    float* spz = fsm + 2*NPT;
    float* sn  = fsm + 3*NPT;

    const int cb = blockIdx.x - BB;        // 0..127
    const int b  = cb >> 4;                // 0..7
    const int g0 = cb & 15;                // 0..15 -> groups g0*8 .. g0*8+7
    const float* base = xyz + (size_t)b*NPT*3;
    for (int j = threadIdx.x; j < NPT; j += 256) {
        float x = base[j*3+0], y = base[j*3+1], z = base[j*3+2];
        spx[j] = x; spy[j] = y; spz[j] = z;
        sn[j]  = x*x + y*y + z*z;
    }
    __syncthreads();

    const int w = threadIdx.x >> 5, l = threadIdx.x & 31;

    for (int jj = 0; jj < 8; jj++) {
        int g = g0*8 + jj;                 // group index within batch (0..127)
        unsigned need = (unsigned)(g*8 + 8);
        if (threadIdx.x == 0) {
            while (*((volatile unsigned*)&g_prog[b]) < need) {}
            __threadfence();
        }
        __syncthreads();

        int cid = (b << 10) + (g << 3) + w;
        float cx = g_nxyz[cid*3+0], cy = g_nxyz[cid*3+1], cz = g_nxyz[cid*3+2];
        float cn = cx*cx + cy*cy + cz*cz;

        float lv = 3.4e38f; int li = 1 << 30;
        float tau = 3.4e38f; int ti = 1 << 30;

        for (int k = 0; k < 128; k++) {
            int j = k*32 + l;
            float dot = cx*spx[j] + cy*spy[j] + cz*spz[j];
            float sq  = cn + sn[j] - 2.0f*dot;
            unsigned mask = __ballot_sync(0xffffffffu, (sq < tau) || (sq == tau && j < ti));
            while (mask) {
                int src = __ffs(mask) - 1;
                mask &= mask - 1;
                float cv = __shfl_sync(0xffffffffu, sq, src);
                int   cj = k*32 + src;
                if (cv < tau || (cv == tau && cj < ti)) {
                    bool less = (l < 16) && ((lv < cv) || (lv == cv && li < cj));
                    unsigned lm = __ballot_sync(0xffffffffu, less);
                    int pos = __popc(lm);
                    float pv = __shfl_up_sync(0xffffffffu, lv, 1);
                    int   pi = __shfl_up_sync(0xffffffffu, li, 1);
                    if (l < 16) {
                        if (l == pos)     { lv = cv; li = cj; }
                        else if (l > pos) { lv = pv; li = pi; }
                    }
                    tau = __shfl_sync(0xffffffffu, lv, 15);
                    ti  = __shfl_sync(0xffffffffu, li, 15);
                }
            }
        }
        if (l < 16) g_knn[cid*16 + l] = li;
        __syncthreads();
        if (threadIdx.x == 0) {
            __threadfence();
            *((volatile unsigned*)&g_kdone[b*128 + g]) = 1u;
        }
    }
}

// software-pipelined fragment MM
template<int KK>
__device__ __forceinline__ void mm_tile(const float* __restrict__ sA, const float* __restrict__ sB,
                                        int ty, int tx, unsigned long long acc[8][4]) {
    const float* pa = sA + ty*8;
    const float* pb = sB + tx*8;
    float4 ca0 = *(const float4*)pa;
    float4 ca1 = *(const float4*)(pa + 4);
    ulonglong2 cb01 = *(const ulonglong2*)pb;
    ulonglong2 cb23 = *(const ulonglong2*)(pb + 4);
#pragma unroll 2
    for (int k = 0; k < KK; k++) {
        float4 na0, na1; ulonglong2 nb01, nb23;
        if (k + 1 < KK) {
            const float* qa = sA + (k+1)*SAST + ty*8;
            const float* qb = sB + (k+1)*CC + tx*8;
            na0  = *(const float4*)qa;
            na1  = *(const float4*)(qa + 4);
            nb01 = *(const ulonglong2*)qb;
            nb23 = *(const ulonglong2*)(qb + 4);
        }
        unsigned long long av[8] = {pk2(ca0.x,ca0.x), pk2(ca0.y,ca0.y), pk2(ca0.z,ca0.z), pk2(ca0.w,ca0.w),
                                    pk2(ca1.x,ca1.x), pk2(ca1.y,ca1.y), pk2(ca1.z,ca1.z), pk2(ca1.w,ca1.w)};
        unsigned long long bv[4] = {cb01.x, cb01.y, cb23.x, cb23.y};
#pragma unroll
        for (int i = 0; i < 8; i++)
#pragma unroll
            for (int j = 0; j < 4; j++) fma2(acc[i][j], av[i], bv[j]);
        ca0 = na0; ca1 = na1; cb01 = nb01; cb23 = nb23;
    }
}

// stats epilogue: per-block column sum/sumsq -> g_part
__device__ __forceinline__ void stats_epilogue(float* red, const float s8[8], const float q8[8],
                                               int ty, int tx, int tid, int blk) {
#pragma unroll
    for (int j = 0; j < 8; j++) {
        red[ty*256 + tx*8 + j]       = s8[j];
        red[ty*256 + 128 + tx*8 + j] = q8[j];
    }
    __syncthreads();
    if (tid < 128) {
        float s = 0.0f, q = 0.0f;
#pragma unroll
        for (int y = 0; y < 16; y++) {
            s += red[y*256 + tid];
            q += red[y*256 + 128 + tid];
        }
        g_part[blk*CC + tid]           = s;
        g_part[1024*CC + blk*CC + tid] = q;
    }
}

// ---------------- GEMM1 body (blocks 136..1159): waits on its kNN group ----------------
__device__ __forceinline__ void gemm1_body(float* sm, const float* __restrict__ xyz,
                                           const float* __restrict__ points,
                                           const float* __restrict__ bias) {
    float* sA = sm;                           // CIN * SAST
    float* sB = sm + CIN*SAST;                // CIN * 128
    __shared__ int   s_nid[128];
    __shared__ float s_ctr[128*3];

    const int gg  = blockIdx.x - (BB + 128);  // 0..1023, group-major across batches
    const int grp = gg >> 3;                  // group-within-batch 0..127
    const int b   = gg & 7;                   // batch
    const int blk = b*128 + grp;              // logical block id (g_part/m0 indexing)
    const int m0  = blk * 128;
    const int tid = threadIdx.x;

    if (tid == 0) {
        while (*((volatile unsigned*)&g_kdone[blk]) == 0u) __nanosleep(128);
        __threadfence();
    }
    __syncthreads();

    if (tid < 128) {
        int gw = m0 + tid;
        s_nid[tid] = g_knn[gw];
        int bk = gw >> 4;
        s_ctr[tid*3+0] = g_nxyz[bk*3+0];
        s_ctr[tid*3+1] = g_nxyz[bk*3+1];
        s_ctr[tid*3+2] = g_nxyz[bk*3+2];
    }
    __syncthreads();

    for (int idx = tid; idx < 128*CIN; idx += 256) {
        int r = idx / CIN, c = idx - r*CIN;
        int nid = s_nid[r];
        float v;
        if (c < 3) v = xyz[((size_t)b*NPT + nid)*3 + c] - s_ctr[r*3 + c];
        else       v = points[((size_t)b*NPT + nid)*DD + (c-3)];
        sA[c*SAST + r] = v;
    }
    for (int idx = tid; idx < CIN*CC; idx += 256) sB[idx] = g_W1T[idx];
    __syncthreads();

    const int ty = tid >> 4, tx = tid & 15;
    unsigned long long acc[8][4];
#pragma unroll
    for (int i = 0; i < 8; i++)
#pragma unroll
        for (int j = 0; j < 4; j++) acc[i][j] = 0ull;

    mm_tile<CIN>(sA, sB, ty, tx, acc);

    float4 q0 = *(const float4*)(bias + tx*8);
    float4 q1 = *(const float4*)(bias + tx*8 + 4);
    float bb[8] = {q0.x,q0.y,q0.z,q0.w,q1.x,q1.y,q1.z,q1.w};
    float s8[8] = {0,0,0,0,0,0,0,0}, sq8[8] = {0,0,0,0,0,0,0,0};
#pragma unroll
    for (int i = 0; i < 8; i++) {
        size_t ro = (size_t)(m0 + ty*8 + i)*CC + tx*8;
        float2 p0 = u2f(acc[i][0]), p1 = u2f(acc[i][1]);
        float2 p2 = u2f(acc[i][2]), p3 = u2f(acc[i][3]);
        float v[8] = {p0.x+bb[0], p0.y+bb[1], p1.x+bb[2], p1.y+bb[3],
                      p2.x+bb[4], p2.y+bb[5], p3.x+bb[6], p3.y+bb[7]};
#pragma unroll
        for (int j = 0; j < 8; j++) { s8[j] += v[j]; sq8[j] = fmaf(v[j], v[j], sq8[j]); }
        *(float4*)(g_h1 + ro)     = make_float4(v[0],v[1],v[2],v[3]);
        *(float4*)(g_h1 + ro + 4) = make_float4(v[4],v[5],v[6],v[7]);
    }
    __syncthreads();
    stats_epilogue(sA, s8, sq8, ty, tx, tid, blk);
}

// ---------------- fused FPS + kNN + GEMM1 (1160 CTAs) ----------------
__global__ void __launch_bounds__(256, 1) fk_kernel(const float* __restrict__ xyz,
                                                    const float* __restrict__ points,
                                                    const float* __restrict__ b1,
                                                    float* __restrict__ outx) {
    extern __shared__ float fsm[];
    if (blockIdx.x < BB)            fps_body(fsm, xyz, outx);
    else if (blockIdx.x < BB + 128) knn_body(fsm, xyz);
    else                            gemm1_body(fsm, xyz, points, b1);
}

// ---------------- GEMM2 (fused stats + group max/min, NO h2 write) ----------------
__global__ void __launch_bounds__(256, 2) gemm2_kernel(const float* __restrict__ bias) {
    extern __shared__ float sm[];
    float* sA = sm;                           // 64 * SAST
    float* sB = sm + 64*SAST;                 // 64 * 128
    const int m0 = blockIdx.x * 128;
    const int tid = threadIdx.x;
    const int ty = tid >> 4, tx = tid & 15;

    unsigned long long acc[8][4];
#pragma unroll
    for (int i = 0; i < 8; i++)
#pragma unroll
        for (int j = 0; j < 4; j++) acc[i][j] = 0ull;

    for (int kc = 0; kc < CC; kc += 64) {
        __syncthreads();
        for (int idx = tid; idx < 128*64; idx += 256) {
            int r = idx >> 6, c = idx & 63;
            int ch = kc + c;
            float x = g_h1[(size_t)(m0 + r)*CC + ch];
            sA[c*SAST + r] = fmaxf(fmaf(x, g_scale[0][ch], g_shift[0][ch]), 0.0f);
        }
        for (int idx = tid; idx < 64*CC; idx += 256) sB[idx] = g_W2T[kc*CC + idx];
        __syncthreads();

        mm_tile<64>(sA, sB, ty, tx, acc);
    }
    float4 q0 = *(const float4*)(bias + tx*8);
    float4 q1 = *(const float4*)(bias + tx*8 + 4);
    float bb[8] = {q0.x,q0.y,q0.z,q0.w,q1.x,q1.y,q1.z,q1.w};
    float s8[8] = {0,0,0,0,0,0,0,0}, sq8[8] = {0,0,0,0,0,0,0,0};
    float mx8[8], mn8[8];
#pragma unroll
    for (int j = 0; j < 8; j++) { mx8[j] = -3.4e38f; mn8[j] = 3.4e38f; }
#pragma unroll
    for (int i = 0; i < 8; i++) {
        float2 p0 = u2f(acc[i][0]), p1 = u2f(acc[i][1]);
        float2 p2 = u2f(acc[i][2]), p3 = u2f(acc[i][3]);
        float v[8] = {p0.x+bb[0], p0.y+bb[1], p1.x+bb[2], p1.y+bb[3],
                      p2.x+bb[4], p2.y+bb[5], p3.x+bb[6], p3.y+bb[7]};
#pragma unroll
        for (int j = 0; j < 8; j++) {
            s8[j] += v[j]; sq8[j] = fmaf(v[j], v[j], sq8[j]);
            mx8[j] = fmaxf(mx8[j], v[j]); mn8[j] = fminf(mn8[j], v[j]);
        }
    }
    __syncthreads();
    stats_epilogue(sA, s8, sq8, ty, tx, tid, blockIdx.x);
    __syncthreads();
#pragma unroll
    for (int j = 0; j < 8; j++) {
        sA[ty*256 + tx*8 + j]       = mx8[j];
        sA[ty*256 + 128 + tx*8 + j] = mn8[j];
    }
    __syncthreads();
    for (int t2 = tid; t2 < 1024; t2 += 256) {
        int g = t2 >> 7, ch = t2 & 127;
        float mx = fmaxf(sA[(2*g)*256 + ch],       sA[(2*g+1)*256 + ch]);
        float mn = fminf(sA[(2*g)*256 + 128 + ch], sA[(2*g+1)*256 + 128 + ch]);
        size_t o = (size_t)(blockIdx.x*8 + g)*CC + ch;
        g_mx[o] = mx; g_mn[o] = mn;
    }
}

// ---------------- BN finalize ----------------
__global__ void bnfin_kernel(int layer, const float* __restrict__ g,
                             const float* __restrict__ be) {
    __shared__ float ss[256], qq[256];
    const int ch = blockIdx.x, tid = threadIdx.x;
    float s = 0.0f, q = 0.0f;
#pragma unroll
    for (int k = 0; k < 4; k++) {
        int i = tid*4 + k;
        s += g_part[i*CC + ch];
        q += g_part[1024*CC + i*CC + ch];
    }
    ss[tid] = s; qq[tid] = q;
    __syncthreads();
    for (int off = 128; off > 0; off >>= 1) {
        if (tid < off) { ss[tid] += ss[tid+off]; qq[tid] += qq[tid+off]; }
        __syncthreads();
    }
    if (tid == 0) {
        float inv = 1.0f / (float)MT;
        float mean = ss[0] * inv;
        float var  = qq[0] * inv - mean*mean;
        float rs   = rsqrtf(var + EPSBN);
        float sc   = rs * g[ch];
        g_scale[layer][ch] = sc;
        g_shift[layer][ch] = be[ch] - mean*sc;
    }
}

// ---------------- final: relu(bn(max-or-min)) ----------------
__global__ void final_kernel(float* __restrict__ out, int off) {
    int bk = blockIdx.x;
    int ch = threadIdx.x;
    float sc = g_scale[1][ch], sh = g_shift[1][ch];
    size_t o = (size_t)bk*CC + ch;
    float v = (sc >= 0.0f) ? g_mx[o] : g_mn[o];
    out[(size_t)off + o] = fmaxf(fmaf(v, sc, sh), 0.0f);
}

// ---------------- launch ----------------
extern "C" void kernel_launch(void* const* d_in, const int* in_sizes, int n_in,
                              void* d_out, int out_size) {
    const float* xyz    = (const float*)d_in[0];
    const float* points = (const float*)d_in[1];
    const float* W1     = (const float*)d_in[2];
    const float* b1     = (const float*)d_in[3];
    const float* g1     = (const float*)d_in[4];
    const float* be1    = (const float*)d_in[5];
    const float* W2     = (const float*)d_in[6];
    const float* b2     = (const float*)d_in[7];
    const float* g2     = (const float*)d_in[8];
    const float* be2    = (const float*)d_in[9];
    float* out = (float*)d_out;

    const int has_xyz = (out_size >= BB*KP*3 + BB*KP*CC) ? 1 : 0;
    float* outx = has_xyz ? out : nullptr;
    const int poff = has_xyz ? BB*KP*3 : 0;

    const int g1_smem = (CIN*SAST + CIN*CC)*(int)sizeof(float);   // 69680 B (covers fps/knn too)
    const int g2_smem = (64*SAST + 64*CC)*(int)sizeof(float);
    cudaFuncSetAttribute(fk_kernel,   cudaFuncAttributeMaxDynamicSharedMemorySize, g1_smem);
    cudaFuncSetAttribute(gemm2_kernel,cudaFuncAttributeMaxDynamicSharedMemorySize, g2_smem);

    wt1_kernel<<<1, 256>>>(W1);          // resets g_prog + g_kdone, transposes W1
    wt2_kernel<<<1, 256>>>(W2);
    fk_kernel<<<BB + 128 + 1024, 256, g1_smem>>>(xyz, points, b1, outx);
    bnfin_kernel<<<CC, 256>>>(0, g1, be1);
    gemm2_kernel<<<MT/128, 256, g2_smem>>>(b2);
    bnfin_kernel<<<CC, 256>>>(1, g2, be2);
    final_kernel<<<BB*KP, 128>>>(out, poff);
}

// round 13
// speedup vs baseline: 1.6724x; 1.6724x over previous
#include <cuda_runtime.h>

#define BB   8
#define NPT  4096
#define DD   64
#define KP   1024
#define NNB  16
#define CC   128
#define CIN  67            // D + 3
#define MT   (BB*KP*NNB)   // 131072 rows
#define EPSBN 1e-5f

// ---------------- scratch ----------------
__device__ float g_h1[(size_t)MT*CC];
__device__ int   g_knn[MT];
__device__ float g_nxyz[BB*KP*3];
__device__ float g_W1T[CIN*CC];
__device__ float g_W2T[CC*CC];
__device__ float g_part[2*1024*CC];
__device__ float g_scale[2][CC];
__device__ float g_shift[2][CC];
__device__ float g_mx[(size_t)BB*KP*CC];
__device__ float g_mn[(size_t)BB*KP*CC];
__device__ unsigned g_prog[BB];            // FPS progress per batch
__device__ unsigned g_kdone[BB*128];       // kNN group-done flags (8 centers/group)

// ---------------- helpers ----------------
__device__ __forceinline__ unsigned redux_max_u32(unsigned v) {
    unsigned r; asm("redux.sync.max.u32 %0,%1,0xffffffff;" : "=r"(r) : "r"(v)); return r;
}
__device__ __forceinline__ unsigned redux_min_u32(unsigned v) {
    unsigned r; asm("redux.sync.min.u32 %0,%1,0xffffffff;" : "=r"(r) : "r"(v)); return r;
}
__device__ __forceinline__ void fma2(unsigned long long& d, unsigned long long a, unsigned long long b) {
    asm("fma.rn.f32x2 %0,%1,%2,%0;" : "+l"(d) : "l"(a), "l"(b));
}
__device__ __forceinline__ unsigned long long mul2(unsigned long long a, unsigned long long b) {
    unsigned long long r; asm("mul.rn.f32x2 %0,%1,%2;" : "=l"(r) : "l"(a), "l"(b)); return r;
}
__device__ __forceinline__ unsigned long long add2(unsigned long long a, unsigned long long b) {
    unsigned long long r; asm("add.rn.f32x2 %0,%1,%2;" : "=l"(r) : "l"(a), "l"(b)); return r;
}
__device__ __forceinline__ unsigned long long pk2(float lo, float hi) {
    unsigned long long r; asm("mov.b64 %0,{%1,%2};" : "=l"(r) : "f"(lo), "f"(hi)); return r;
}
__device__ __forceinline__ float2 u2f(unsigned long long v) {
    float2 f; asm("mov.b64 {%0,%1},%2;" : "=f"(f.x), "=f"(f.y) : "l"(v)); return f;
}

// ---------------- pre-kernels ----------------
__global__ void wt1_kernel(const float* __restrict__ W1) {
    if (threadIdx.x < BB) g_prog[threadIdx.x] = 0u;
    for (int i = threadIdx.x; i < BB*128; i += blockDim.x) g_kdone[i] = 0u;
    for (int idx = threadIdx.x; idx < CC*CIN; idx += blockDim.x) {
        int o = idx / CIN, c = idx - o*CIN;
        g_W1T[c*CC + o] = W1[idx];
    }
}
__global__ void wt2_kernel(const float* __restrict__ W2) {
    for (int idx = threadIdx.x; idx < CC*CC; idx += blockDim.x) {
        int o = idx >> 7, c = idx & 127;
        g_W2T[c*CC + o] = W2[idx];
    }
}
__global__ void zz_kernel() {   // filler: keeps fk at ncu capture slot
    g_part[blockIdx.x * blockDim.x + threadIdx.x] = 0.0f;
}

#define SAST 132   // scalar A tile stride (floats)

// ---------------- FPS body (blocks 0..7) ----------------
__device__ __forceinline__ void fps_body(float* fsm, const float* __restrict__ xyz,
                                         float* __restrict__ outx) {
    float4* sp = (float4*)fsm;
    unsigned* vslot = (unsigned*)(sp + NPT);
    unsigned* islot = vslot + 16;

    const int b    = blockIdx.x;
    const int st   = threadIdx.x;
    const int lane = st & 31, warp = st >> 5;
    const float* base = xyz + (size_t)b*NPT*3;

    float c[48];
    {
        const float4* s4 = (const float4*)(base + st*48);
#pragma unroll
        for (int q = 0; q < 12; q++) {
            float4 v = s4[q];
            c[4*q+0] = v.x; c[4*q+1] = v.y; c[4*q+2] = v.z; c[4*q+3] = v.w;
        }
    }
    unsigned long long pxp[8], pyp[8], pzp[8];
    float dist[16];
#pragma unroll
    for (int q = 0; q < 8; q++) {
        pxp[q] = pk2(c[6*q+0], c[6*q+3]);
        pyp[q] = pk2(c[6*q+1], c[6*q+4]);
        pzp[q] = pk2(c[6*q+2], c[6*q+5]);
        dist[2*q] = 1e10f; dist[2*q+1] = 1e10f;
    }
#pragma unroll
    for (int i = 0; i < 16; i++)
        sp[st*16 + i] = make_float4(c[3*i+0], c[3*i+1], c[3*i+2], 0.0f);
    __syncthreads();

    int far = 0;
    for (int t = 0; t < KP; t++) {
        float4 ctr = sp[far];
        if (st == 0) {
            int o = (b*KP + t)*3;
            g_nxyz[o+0] = ctr.x; g_nxyz[o+1] = ctr.y; g_nxyz[o+2] = ctr.z;
            if (outx) { outx[o+0] = ctr.x; outx[o+1] = ctr.y; outx[o+2] = ctr.z; }
            if ((t & 7) == 7) {
                __threadfence();
                *((volatile unsigned*)&g_prog[b]) = (unsigned)(t + 1);
            }
        }
        unsigned long long ncx = pk2(-ctr.x, -ctr.x), ncy = pk2(-ctr.y, -ctr.y), ncz = pk2(-ctr.z, -ctr.z);
#pragma unroll
        for (int q = 0; q < 8; q++) {
            unsigned long long dx = add2(pxp[q], ncx);
            unsigned long long dy = add2(pyp[q], ncy);
            unsigned long long dz = add2(pzp[q], ncz);
            unsigned long long dd = mul2(dx, dx);
            fma2(dd, dy, dy);
            fma2(dd, dz, dz);
            float2 e = u2f(dd);
            dist[2*q]   = fminf(dist[2*q],   e.x);
            dist[2*q+1] = fminf(dist[2*q+1], e.y);
        }
        float h[8];
#pragma unroll
        for (int i = 0; i < 8; i++) h[i] = fmaxf(dist[2*i], dist[2*i+1]);
        float h0 = fmaxf(fmaxf(h[0], h[1]), fmaxf(h[2], h[3]));
        float h1 = fmaxf(fmaxf(h[4], h[5]), fmaxf(h[6], h[7]));
        float tm = fmaxf(h0, h1);
        unsigned mb = redux_max_u32(__float_as_uint(tm));
        float m = __uint_as_float(mb);
        int li = 15;
#pragma unroll
        for (int i = 14; i >= 0; i--) li = (dist[i] == m) ? i : li;
        unsigned widx = redux_min_u32((__float_as_uint(tm) == mb)
                                      ? (unsigned)(st*16 + li) : 0xFFFFFFFFu);
        const int par = (t & 1) * 8;
        if (lane == 0) { vslot[par + warp] = mb; islot[par + warp] = widx; }
        __syncthreads();
        unsigned v  = vslot[par + (lane & 7)];
        unsigned iv = islot[par + (lane & 7)];
        unsigned m2 = redux_max_u32(v);
        far = (int)redux_min_u32((v == m2) ? iv : 0xFFFFFFFFu);
    }
    if (st == 0) {
        __threadfence();
        *((volatile unsigned*)&g_prog[b]) = (unsigned)KP;
    }
}

// ---------------- kNN body (blocks 8..135): contiguous groups, publish flags ----------------
__device__ __forceinline__ void knn_body(float* fsm, const float* __restrict__ xyz) {
    float* spx = fsm;
    float* spy = fsm + NPT;
    float* spz = fsm + 2*NPT;
    float* sn  = fsm + 3*NPT;

    const int cb = blockIdx.x - BB;        // 0..127
    const int b  = cb >> 4;                // 0..7
    const int g0 = cb & 15;                // groups g0*8 .. g0*8+7
    const float* base = xyz + (size_t)b*NPT*3;
    for (int j = threadIdx.x; j < NPT; j += 256) {
        float x = base[j*3+0], y = base[j*3+1], z = base[j*3+2];
        spx[j] = x; spy[j] = y; spz[j] = z;
        sn[j]  = x*x + y*y + z*z;
    }
    __syncthreads();

    const int w = threadIdx.x >> 5, l = threadIdx.x & 31;

    for (int jj = 0; jj < 8; jj++) {
        int g = g0*8 + jj;
        unsigned need = (unsigned)(g*8 + 8);
        if (threadIdx.x == 0) {
            while (*((volatile unsigned*)&g_prog[b]) < need) {}
            __threadfence();
        }
        __syncthreads();

        int cid = (b << 10) + (g << 3) + w;
        float cx = g_nxyz[cid*3+0], cy = g_nxyz[cid*3+1], cz = g_nxyz[cid*3+2];
        float cn = cx*cx + cy*cy + cz*cz;

        float lv = 3.4e38f; int li = 1 << 30;
        float tau = 3.4e38f; int ti = 1 << 30;

        for (int k = 0; k < 128; k++) {
            int j = k*32 + l;
            float dot = cx*spx[j] + cy*spy[j] + cz*spz[j];
            float sq  = cn + sn[j] - 2.0f*dot;
            unsigned mask = __ballot_sync(0xffffffffu, (sq < tau) || (sq == tau && j < ti));
            while (mask) {
                int src = __ffs(mask) - 1;
                mask &= mask - 1;
                float cv = __shfl_sync(0xffffffffu, sq, src);
                int   cj = k*32 + src;
                if (cv < tau || (cv == tau && cj < ti)) {
                    bool less = (l < 16) && ((lv < cv) || (lv == cv && li < cj));
                    unsigned lm = __ballot_sync(0xffffffffu, less);
                    int pos = __popc(lm);
                    float pv = __shfl_up_sync(0xffffffffu, lv, 1);
                    int   pi = __shfl_up_sync(0xffffffffu, li, 1);
                    if (l < 16) {
                        if (l == pos)     { lv = cv; li = cj; }
                        else if (l > pos) { lv = pv; li = pi; }
                    }
                    tau = __shfl_sync(0xffffffffu, lv, 15);
                    ti  = __shfl_sync(0xffffffffu, li, 15);
                }
            }
        }
        if (l < 16) g_knn[cid*16 + l] = li;
        __syncthreads();
        if (threadIdx.x == 0) {
            __threadfence();
            *((volatile unsigned*)&g_kdone[b*128 + g]) = 1u;
        }
    }
}

// software-pipelined fragment MM
template<int KK>
__device__ __forceinline__ void mm_tile(const float* __restrict__ sA, const float* __restrict__ sB,
                                        int ty, int tx, unsigned long long acc[8][4]) {
    const float* pa = sA + ty*8;
    const float* pb = sB + tx*8;
    float4 ca0 = *(const float4*)pa;
    float4 ca1 = *(const float4*)(pa + 4);
    ulonglong2 cb01 = *(const ulonglong2*)pb;
    ulonglong2 cb23 = *(const ulonglong2*)(pb + 4);
#pragma unroll 2
    for (int k = 0; k < KK; k++) {
        float4 na0, na1; ulonglong2 nb01, nb23;
        if (k + 1 < KK) {
            const float* qa = sA + (k+1)*SAST + ty*8;
            const float* qb = sB + (k+1)*CC + tx*8;
            na0  = *(const float4*)qa;
            na1  = *(const float4*)(qa + 4);
            nb01 = *(const ulonglong2*)qb;
            nb23 = *(const ulonglong2*)(qb + 4);
        }
        unsigned long long av[8] = {pk2(ca0.x,ca0.x), pk2(ca0.y,ca0.y), pk2(ca0.z,ca0.z), pk2(ca0.w,ca0.w),
                                    pk2(ca1.x,ca1.x), pk2(ca1.y,ca1.y), pk2(ca1.z,ca1.z), pk2(ca1.w,ca1.w)};
        unsigned long long bv[4] = {cb01.x, cb01.y, cb23.x, cb23.y};
#pragma unroll
        for (int i = 0; i < 8; i++)
#pragma unroll
            for (int j = 0; j < 4; j++) fma2(acc[i][j], av[i], bv[j]);
        ca0 = na0; ca1 = na1; cb01 = nb01; cb23 = nb23;
    }
}

// stats epilogue: per-block column sum/sumsq -> g_part
__device__ __forceinline__ void stats_epilogue(float* red, const float s8[8], const float q8[8],
                                               int ty, int tx, int tid, int blk) {
#pragma unroll
    for (int j = 0; j < 8; j++) {
        red[ty*256 + tx*8 + j]       = s8[j];
        red[ty*256 + 128 + tx*8 + j] = q8[j];
    }
    __syncthreads();
    if (tid < 128) {
        float s = 0.0f, q = 0.0f;
#pragma unroll
        for (int y = 0; y < 16; y++) {
            s += red[y*256 + tid];
            q += red[y*256 + 128 + tid];
        }
        g_part[blk*CC + tid]           = s;
        g_part[1024*CC + blk*CC + tid] = q;
    }
}

// ---------------- GEMM1 body (blocks 136..1159): waits on its kNN group ----------------
__device__ __forceinline__ void gemm1_body(float* sm, const float* __restrict__ xyz,
                                           const float* __restrict__ points,
                                           const float* __restrict__ bias) {
    float* sA = sm;                           // CIN * SAST
    float* sB = sm + CIN*SAST;                // CIN * 128
    __shared__ int   s_nid[128];
    __shared__ float s_ctr[128*3];

    const int gg  = blockIdx.x - (BB + 128);  // 0..1023, group-major across batches
    const int grp = gg >> 3;
    const int b   = gg & 7;
    const int blk = b*128 + grp;
    const int m0  = blk * 128;
    const int tid = threadIdx.x;

    if (tid == 0) {
        while (*((volatile unsigned*)&g_kdone[blk]) == 0u) __nanosleep(128);
        __threadfence();
    }
    __syncthreads();

    if (tid < 128) {
        int gw = m0 + tid;
        s_nid[tid] = g_knn[gw];
        int bk = gw >> 4;
        s_ctr[tid*3+0] = g_nxyz[bk*3+0];
        s_ctr[tid*3+1] = g_nxyz[bk*3+1];
        s_ctr[tid*3+2] = g_nxyz[bk*3+2];
    }
    __syncthreads();

    for (int idx = tid; idx < 128*CIN; idx += 256) {
        int r = idx / CIN, c = idx - r*CIN;
        int nid = s_nid[r];
        float v;
        if (c < 3) v = xyz[((size_t)b*NPT + nid)*3 + c] - s_ctr[r*3 + c];
        else       v = points[((size_t)b*NPT + nid)*DD + (c-3)];
        sA[c*SAST + r] = v;
    }
    for (int idx = tid; idx < CIN*CC; idx += 256) sB[idx] = g_W1T[idx];
    __syncthreads();

    const int ty = tid >> 4, tx = tid & 15;
    unsigned long long acc[8][4];
#pragma unroll
    for (int i = 0; i < 8; i++)
#pragma unroll
        for (int j = 0; j < 4; j++) acc[i][j] = 0ull;

    mm_tile<CIN>(sA, sB, ty, tx, acc);

    float4 q0 = *(const float4*)(bias + tx*8);
    float4 q1 = *(const float4*)(bias + tx*8 + 4);
    float bb[8] = {q0.x,q0.y,q0.z,q0.w,q1.x,q1.y,q1.z,q1.w};
    float s8[8] = {0,0,0,0,0,0,0,0}, sq8[8] = {0,0,0,0,0,0,0,0};
#pragma unroll
    for (int i = 0; i < 8; i++) {
        size_t ro = (size_t)(m0 + ty*8 + i)*CC + tx*8;
        float2 p0 = u2f(acc[i][0]), p1 = u2f(acc[i][1]);
        float2 p2 = u2f(acc[i][2]), p3 = u2f(acc[i][3]);
        float v[8] = {p0.x+bb[0], p0.y+bb[1], p1.x+bb[2], p1.y+bb[3],
                      p2.x+bb[4], p2.y+bb[5], p3.x+bb[6], p3.y+bb[7]};
#pragma unroll
        for (int j = 0; j < 8; j++) { s8[j] += v[j]; sq8[j] = fmaf(v[j], v[j], sq8[j]); }
        *(float4*)(g_h1 + ro)     = make_float4(v[0],v[1],v[2],v[3]);
        *(float4*)(g_h1 + ro + 4) = make_float4(v[4],v[5],v[6],v[7]);
    }
    __syncthreads();
    stats_epilogue(sA, s8, sq8, ty, tx, tid, blk);
}

// ---------------- fused FPS + kNN + GEMM1 (1160 CTAs, 1 CTA/SM enforced by smem) ----------------
__global__ void __launch_bounds__(256, 1) fk_kernel(const float* __restrict__ xyz,
                                                    const float* __restrict__ points,
                                                    const float* __restrict__ b1,
                                                    float* __restrict__ outx) {
    extern __shared__ float fsm[];
    if (blockIdx.x < BB)            fps_body(fsm, xyz, outx);
    else if (blockIdx.x < BB + 128) knn_body(fsm, xyz);
    else                            gemm1_body(fsm, xyz, points, b1);
}

// ---------------- GEMM2 (fused stats + group max/min, NO h2 write) ----------------
__global__ void __launch_bounds__(256, 2) gemm2_kernel(const float* __restrict__ bias) {
    extern __shared__ float sm[];
    float* sA = sm;                           // 64 * SAST
    float* sB = sm + 64*SAST;                 // 64 * 128
    const int m0 = blockIdx.x * 128;
    const int tid = threadIdx.x;
    const int ty = tid >> 4, tx = tid & 15;

    unsigned long long acc[8][4];
#pragma unroll
    for (int i = 0; i < 8; i++)
#pragma unroll
        for (int j = 0; j < 4; j++) acc[i][j] = 0ull;

    for (int kc = 0; kc < CC; kc += 64) {
        __syncthreads();
        for (int idx = tid; idx < 128*64; idx += 256) {
            int r = idx >> 6, c = idx & 63;
            int ch = kc + c;
            float x = g_h1[(size_t)(m0 + r)*CC + ch];
            sA[c*SAST + r] = fmaxf(fmaf(x, g_scale[0][ch], g_shift[0][ch]), 0.0f);
        }
        for (int idx = tid; idx < 64*CC; idx += 256) sB[idx] = g_W2T[kc*CC + idx];
        __syncthreads();

        mm_tile<64>(sA, sB, ty, tx, acc);
    }
    float4 q0 = *(const float4*)(bias + tx*8);
    float4 q1 = *(const float4*)(bias + tx*8 + 4);
    float bb[8] = {q0.x,q0.y,q0.z,q0.w,q1.x,q1.y,q1.z,q1.w};
    float s8[8] = {0,0,0,0,0,0,0,0}, sq8[8] = {0,0,0,0,0,0,0,0};
    float mx8[8], mn8[8];
#pragma unroll
    for (int j = 0; j < 8; j++) { mx8[j] = -3.4e38f; mn8[j] = 3.4e38f; }
#pragma unroll
    for (int i = 0; i < 8; i++) {
        float2 p0 = u2f(acc[i][0]), p1 = u2f(acc[i][1]);
        float2 p2 = u2f(acc[i][2]), p3 = u2f(acc[i][3]);
        float v[8] = {p0.x+bb[0], p0.y+bb[1], p1.x+bb[2], p1.y+bb[3],
                      p2.x+bb[4], p2.y+bb[5], p3.x+bb[6], p3.y+bb[7]};
#pragma unroll
        for (int j = 0; j < 8; j++) {
            s8[j] += v[j]; sq8[j] = fmaf(v[j], v[j], sq8[j]);
            mx8[j] = fmaxf(mx8[j], v[j]); mn8[j] = fminf(mn8[j], v[j]);
        }
    }
    __syncthreads();
    stats_epilogue(sA, s8, sq8, ty, tx, tid, blockIdx.x);
    __syncthreads();
#pragma unroll
    for (int j = 0; j < 8; j++) {
        sA[ty*256 + tx*8 + j]       = mx8[j];
        sA[ty*256 + 128 + tx*8 + j] = mn8[j];
    }
    __syncthreads();
    for (int t2 = tid; t2 < 1024; t2 += 256) {
        int g = t2 >> 7, ch = t2 & 127;
        float mx = fmaxf(sA[(2*g)*256 + ch],       sA[(2*g+1)*256 + ch]);
        float mn = fminf(sA[(2*g)*256 + 128 + ch], sA[(2*g+1)*256 + 128 + ch]);
        size_t o = (size_t)(blockIdx.x*8 + g)*CC + ch;
        g_mx[o] = mx; g_mn[o] = mn;
    }
}

// ---------------- BN finalize ----------------
__global__ void bnfin_kernel(int layer, const float* __restrict__ g,
                             const float* __restrict__ be) {
    __shared__ float ss[256], qq[256];
    const int ch = blockIdx.x, tid = threadIdx.x;
    float s = 0.0f, q = 0.0f;
#pragma unroll
    for (int k = 0; k < 4; k++) {
        int i = tid*4 + k;
        s += g_part[i*CC + ch];
        q += g_part[1024*CC + i*CC + ch];
    }
    ss[tid] = s; qq[tid] = q;
    __syncthreads();
    for (int off = 128; off > 0; off >>= 1) {
        if (tid < off) { ss[tid] += ss[tid+off]; qq[tid] += qq[tid+off]; }
        __syncthreads();
    }
    if (tid == 0) {
        float inv = 1.0f / (float)MT;
        float mean = ss[0] * inv;
        float var  = qq[0] * inv - mean*mean;
        float rs   = rsqrtf(var + EPSBN);
        float sc   = rs * g[ch];
        g_scale[layer][ch] = sc;
        g_shift[layer][ch] = be[ch] - mean*sc;
    }
}

// ---------------- final: relu(bn(max-or-min)) ----------------
__global__ void final_kernel(float* __restrict__ out, int off) {
    int bk = blockIdx.x;
    int ch = threadIdx.x;
    float sc = g_scale[1][ch], sh = g_shift[1][ch];
    size_t o = (size_t)bk*CC + ch;
    float v = (sc >= 0.0f) ? g_mx[o] : g_mn[o];
    out[(size_t)off + o] = fmaxf(fmaf(v, sc, sh), 0.0f);
}

// ---------------- launch ----------------
extern "C" void kernel_launch(void* const* d_in, const int* in_sizes, int n_in,
                              void* d_out, int out_size) {
    const float* xyz    = (const float*)d_in[0];
    const float* points = (const float*)d_in[1];
    const float* W1     = (const float*)d_in[2];
    const float* b1     = (const float*)d_in[3];
    const float* g1     = (const float*)d_in[4];
    const float* be1    = (const float*)d_in[5];
    const float* W2     = (const float*)d_in[6];
    const float* b2     = (const float*)d_in[7];
    const float* g2     = (const float*)d_in[8];
    const float* be2    = (const float*)d_in[9];
    float* out = (float*)d_out;

    const int has_xyz = (out_size >= BB*KP*3 + BB*KP*CC) ? 1 : 0;
    float* outx = has_xyz ? out : nullptr;
    const int poff = has_xyz ? BB*KP*3 : 0;

    // 120KB dynamic smem: 2 CTAs can't fit in the 228KB carveout -> 1 CTA/SM, FPS keeps
    // its SM exclusively (R12's co-residency regression fix).
    const int fk_smem = 120*1024;
    const int g2_smem = (64*SAST + 64*CC)*(int)sizeof(float);
    cudaFuncSetAttribute(fk_kernel,   cudaFuncAttributeMaxDynamicSharedMemorySize, fk_smem);
    cudaFuncSetAttribute(gemm2_kernel,cudaFuncAttributeMaxDynamicSharedMemorySize, g2_smem);

    wt1_kernel<<<1, 256>>>(W1);          // resets g_prog + g_kdone, transposes W1
    wt2_kernel<<<1, 256>>>(W2);
    zz_kernel<<<64, 256>>>();            // filler so ncu captures fk
    fk_kernel<<<BB + 128 + 1024, 256, fk_smem>>>(xyz, points, b1, outx);
    bnfin_kernel<<<CC, 256>>>(0, g1, be1);
    gemm2_kernel<<<MT/128, 256, g2_smem>>>(b2);
    bnfin_kernel<<<CC, 256>>>(1, g2, be2);
    final_kernel<<<BB*KP, 128>>>(out, poff);
}

// round 14
// speedup vs baseline: 2.2030x; 1.3173x over previous
#include <cuda_runtime.h>

#define BB   8
#define NPT  4096
#define DD   64
#define KP   1024
#define NNB  16
#define CC   128
#define CIN  67            // D + 3
#define MT   (BB*KP*NNB)   // 131072 rows
#define EPSBN 1e-5f

// ---------------- scratch ----------------
__device__ float g_h1[(size_t)MT*CC];
__device__ float g_nxyz[BB*KP*3];
__device__ float g_W1T[CIN*CC];
__device__ float g_W2T[CC*CC];
__device__ float g_part[2*1024*CC];
__device__ float g_scale[2][CC];
__device__ float g_shift[2][CC];
__device__ float g_mx[(size_t)BB*KP*CC];
__device__ float g_mn[(size_t)BB*KP*CC];
__device__ unsigned g_prog[BB];            // FPS progress per batch

// ---------------- helpers ----------------
__device__ __forceinline__ unsigned redux_max_u32(unsigned v) {
    unsigned r; asm("redux.sync.max.u32 %0,%1,0xffffffff;" : "=r"(r) : "r"(v)); return r;
}
__device__ __forceinline__ unsigned redux_min_u32(unsigned v) {
    unsigned r; asm("redux.sync.min.u32 %0,%1,0xffffffff;" : "=r"(r) : "r"(v)); return r;
}
__device__ __forceinline__ void fma2(unsigned long long& d, unsigned long long a, unsigned long long b) {
    asm("fma.rn.f32x2 %0,%1,%2,%0;" : "+l"(d) : "l"(a), "l"(b));
}
__device__ __forceinline__ unsigned long long mul2(unsigned long long a, unsigned long long b) {
    unsigned long long r; asm("mul.rn.f32x2 %0,%1,%2;" : "=l"(r) : "l"(a), "l"(b)); return r;
}
__device__ __forceinline__ unsigned long long add2(unsigned long long a, unsigned long long b) {
    unsigned long long r; asm("add.rn.f32x2 %0,%1,%2;" : "=l"(r) : "l"(a), "l"(b)); return r;
}
__device__ __forceinline__ unsigned long long pk2(float lo, float hi) {
    unsigned long long r; asm("mov.b64 %0,{%1,%2};" : "=l"(r) : "f"(lo), "f"(hi)); return r;
}
__device__ __forceinline__ float2 u2f(unsigned long long v) {
    float2 f; asm("mov.b64 {%0,%1},%2;" : "=f"(f.x), "=f"(f.y) : "l"(v)); return f;
}

// ---------------- pre-kernels ----------------
__global__ void wt1_kernel(const float* __restrict__ W1) {
    if (threadIdx.x < BB) g_prog[threadIdx.x] = 0u;
    for (int idx = threadIdx.x; idx < CC*CIN; idx += blockDim.x) {
        int o = idx / CIN, c = idx - o*CIN;
        g_W1T[c*CC + o] = W1[idx];
    }
}
__global__ void wt2_kernel(const float* __restrict__ W2) {
    for (int idx = threadIdx.x; idx < CC*CC; idx += blockDim.x) {
        int o = idx >> 7, c = idx & 127;
        g_W2T[c*CC + o] = W2[idx];
    }
}
__global__ void zz_kernel() {   // filler: keeps fk at ncu capture slot
    g_part[blockIdx.x * blockDim.x + threadIdx.x] = 0.0f;
}

#define SAST 132   // scalar A tile stride (floats)

// software-pipelined fragment MM
template<int KK>
__device__ __forceinline__ void mm_tile(const float* __restrict__ sA, const float* __restrict__ sB,
                                        int ty, int tx, unsigned long long acc[8][4]) {
    const float* pa = sA + ty*8;
    const float* pb = sB + tx*8;
    float4 ca0 = *(const float4*)pa;
    float4 ca1 = *(const float4*)(pa + 4);
    ulonglong2 cb01 = *(const ulonglong2*)pb;
    ulonglong2 cb23 = *(const ulonglong2*)(pb + 4);
#pragma unroll 2
    for (int k = 0; k < KK; k++) {
        float4 na0, na1; ulonglong2 nb01, nb23;
        if (k + 1 < KK) {
            const float* qa = sA + (k+1)*SAST + ty*8;
            const float* qb = sB + (k+1)*CC + tx*8;
            na0  = *(const float4*)qa;
            na1  = *(const float4*)(qa + 4);
            nb01 = *(const ulonglong2*)qb;
            nb23 = *(const ulonglong2*)(qb + 4);
        }
        unsigned long long av[8] = {pk2(ca0.x,ca0.x), pk2(ca0.y,ca0.y), pk2(ca0.z,ca0.z), pk2(ca0.w,ca0.w),
                                    pk2(ca1.x,ca1.x), pk2(ca1.y,ca1.y), pk2(ca1.z,ca1.z), pk2(ca1.w,ca1.w)};
        unsigned long long bv[4] = {cb01.x, cb01.y, cb23.x, cb23.y};
#pragma unroll
        for (int i = 0; i < 8; i++)
#pragma unroll
            for (int j = 0; j < 4; j++) fma2(acc[i][j], av[i], bv[j]);
        ca0 = na0; ca1 = na1; cb01 = nb01; cb23 = nb23;
    }
}

// stats epilogue: per-block column sum/sumsq -> g_part (red: >=16*256 floats)
__device__ __forceinline__ void stats_epilogue(float* red, const float s8[8], const float q8[8],
                                               int ty, int tx, int tid, int blk) {
#pragma unroll
    for (int j = 0; j < 8; j++) {
        red[ty*256 + tx*8 + j]       = s8[j];
        red[ty*256 + 128 + tx*8 + j] = q8[j];
    }
    __syncthreads();
    if (tid < 128) {
        float s = 0.0f, q = 0.0f;
#pragma unroll
        for (int y = 0; y < 16; y++) {
            s += red[y*256 + tid];
            q += red[y*256 + 128 + tid];
        }
        g_part[blk*CC + tid]           = s;
        g_part[1024*CC + blk*CC + tid] = q;
    }
}

// ---------------- FPS body (blocks 0..7) ----------------
__device__ __forceinline__ void fps_body(float* fsm, const float* __restrict__ xyz,
                                         float* __restrict__ outx) {
    float4* sp = (float4*)fsm;
    unsigned* vslot = (unsigned*)(sp + NPT);
    unsigned* islot = vslot + 16;

    const int b    = blockIdx.x;
    const int st   = threadIdx.x;
    const int lane = st & 31, warp = st >> 5;
    const float* base = xyz + (size_t)b*NPT*3;

    float c[48];
    {
        const float4* s4 = (const float4*)(base + st*48);
#pragma unroll
        for (int q = 0; q < 12; q++) {
            float4 v = s4[q];
            c[4*q+0] = v.x; c[4*q+1] = v.y; c[4*q+2] = v.z; c[4*q+3] = v.w;
        }
    }
    unsigned long long pxp[8], pyp[8], pzp[8];
    float dist[16];
#pragma unroll
    for (int q = 0; q < 8; q++) {
        pxp[q] = pk2(c[6*q+0], c[6*q+3]);
        pyp[q] = pk2(c[6*q+1], c[6*q+4]);
        pzp[q] = pk2(c[6*q+2], c[6*q+5]);
        dist[2*q] = 1e10f; dist[2*q+1] = 1e10f;
    }
#pragma unroll
    for (int i = 0; i < 16; i++)
        sp[st*16 + i] = make_float4(c[3*i+0], c[3*i+1], c[3*i+2], 0.0f);
    __syncthreads();

    int far = 0;
    for (int t = 0; t < KP; t++) {
        float4 ctr = sp[far];
        if (st == 0) {
            int o = (b*KP + t)*3;
            g_nxyz[o+0] = ctr.x; g_nxyz[o+1] = ctr.y; g_nxyz[o+2] = ctr.z;
            if (outx) { outx[o+0] = ctr.x; outx[o+1] = ctr.y; outx[o+2] = ctr.z; }
            if ((t & 7) == 7) {
                __threadfence();
                *((volatile unsigned*)&g_prog[b]) = (unsigned)(t + 1);
            }
        }
        unsigned long long ncx = pk2(-ctr.x, -ctr.x), ncy = pk2(-ctr.y, -ctr.y), ncz = pk2(-ctr.z, -ctr.z);
#pragma unroll
        for (int q = 0; q < 8; q++) {
            unsigned long long dx = add2(pxp[q], ncx);
            unsigned long long dy = add2(pyp[q], ncy);
            unsigned long long dz = add2(pzp[q], ncz);
            unsigned long long dd = mul2(dx, dx);
            fma2(dd, dy, dy);
            fma2(dd, dz, dz);
            float2 e = u2f(dd);
            dist[2*q]   = fminf(dist[2*q],   e.x);
            dist[2*q+1] = fminf(dist[2*q+1], e.y);
        }
        float h[8];
#pragma unroll
        for (int i = 0; i < 8; i++) h[i] = fmaxf(dist[2*i], dist[2*i+1]);
        float h0 = fmaxf(fmaxf(h[0], h[1]), fmaxf(h[2], h[3]));
        float h1 = fmaxf(fmaxf(h[4], h[5]), fmaxf(h[6], h[7]));
        float tm = fmaxf(h0, h1);
        unsigned mb = redux_max_u32(__float_as_uint(tm));
        float m = __uint_as_float(mb);
        int li = 15;
#pragma unroll
        for (int i = 14; i >= 0; i--) li = (dist[i] == m) ? i : li;
        unsigned widx = redux_min_u32((__float_as_uint(tm) == mb)
                                      ? (unsigned)(st*16 + li) : 0xFFFFFFFFu);
        const int par = (t & 1) * 8;
        if (lane == 0) { vslot[par + warp] = mb; islot[par + warp] = widx; }
        __syncthreads();
        unsigned v  = vslot[par + (lane & 7)];
        unsigned iv = islot[par + (lane & 7)];
        unsigned m2 = redux_max_u32(v);
        far = (int)redux_min_u32((v == m2) ? iv : 0xFFFFFFFFu);
    }
    if (st == 0) {
        __threadfence();
        *((volatile unsigned*)&g_prog[b]) = (unsigned)KP;
    }
}

// ---------------- kNN + GEMM1 fused body (blocks 8..135) ----------------
// Each CTA: one batch tile, 8 strided groups; per group: top-16 kNN (8 warps,
// 1 center each) -> immediately that group's GEMM1 block. No flags, no g_knn.
__device__ __forceinline__ void knng1_body(float* fsm, const float* __restrict__ xyz,
                                           const float* __restrict__ points,
                                           const float* __restrict__ bias) {
    float* spx = fsm;
    float* spy = fsm + NPT;
    float* spz = fsm + 2*NPT;
    float* sn  = fsm + 3*NPT;
    float* sA  = fsm + 4*NPT;             // CIN*SAST
    float* sB  = sA + CIN*SAST;           // CIN*CC
    __shared__ int   s_nid[128];
    __shared__ float s_ctr[24];

    const int cb = blockIdx.x - BB;        // 0..127
    const int b  = cb >> 4;                // batch 0..7
    const int g0 = cb & 15;                // stride phase
    const int tid = threadIdx.x;
    const float* base = xyz + (size_t)b*NPT*3;

    for (int j = tid; j < NPT; j += 256) {
        float x = base[j*3+0], y = base[j*3+1], z = base[j*3+2];
        spx[j] = x; spy[j] = y; spz[j] = z;
        sn[j]  = x*x + y*y + z*z;
    }
    for (int idx = tid; idx < CIN*CC; idx += 256) sB[idx] = g_W1T[idx];   // once per CTA
    __syncthreads();

    const int w = tid >> 5, l = tid & 31;
    const int ty = tid >> 4, tx = tid & 15;

    for (int jj = 0; jj < 8; jj++) {
        const int g   = jj*16 + g0;        // strided: matches FPS production pace
        const int blk = b*128 + g;
        const int m0  = blk * 128;

        if (tid == 0) {
            unsigned need = (unsigned)(g*8 + 8);
            while (*((volatile unsigned*)&g_prog[b]) < need) {}
            __threadfence();
        }
        __syncthreads();

        // ---- kNN: warp w handles center (blk*8 + w) ----
        {
            int cid = blk*8 + w;
            float cx = g_nxyz[cid*3+0], cy = g_nxyz[cid*3+1], cz = g_nxyz[cid*3+2];
            float cn = cx*cx + cy*cy + cz*cz;

            float lv = 3.4e38f; int li = 1 << 30;
            float tau = 3.4e38f; int ti = 1 << 30;

            for (int k = 0; k < 128; k++) {
                int j = k*32 + l;
                float dot = cx*spx[j] + cy*spy[j] + cz*spz[j];
                float sq  = cn + sn[j] - 2.0f*dot;
                unsigned mask = __ballot_sync(0xffffffffu, (sq < tau) || (sq == tau && j < ti));
                while (mask) {
                    int src = __ffs(mask) - 1;
                    mask &= mask - 1;
                    float cv = __shfl_sync(0xffffffffu, sq, src);
                    int   cj = k*32 + src;
                    if (cv < tau || (cv == tau && cj < ti)) {
                        bool less = (l < 16) && ((lv < cv) || (lv == cv && li < cj));
                        unsigned lm = __ballot_sync(0xffffffffu, less);
                        int pos = __popc(lm);
                        float pv = __shfl_up_sync(0xffffffffu, lv, 1);
                        int   pi = __shfl_up_sync(0xffffffffu, li, 1);
                        if (l < 16) {
                            if (l == pos)     { lv = cv; li = cj; }
                            else if (l > pos) { lv = pv; li = pi; }
                        }
                        tau = __shfl_sync(0xffffffffu, lv, 15);
                        ti  = __shfl_sync(0xffffffffu, li, 15);
                    }
                }
            }
            if (l < 16) s_nid[w*16 + l] = li;
        }
        if (tid < 24) s_ctr[tid] = g_nxyz[blk*24 + tid];
        __syncthreads();

        // ---- GEMM1 for this group's 128 rows ----
        for (int idx = tid; idx < 128*CIN; idx += 256) {
            int r = idx / CIN, c = idx - r*CIN;
            int nid = s_nid[r];
            float v;
            if (c < 3) v = xyz[((size_t)b*NPT + nid)*3 + c] - s_ctr[(r>>4)*3 + c];
            else       v = points[((size_t)b*NPT + nid)*DD + (c-3)];
            sA[c*SAST + r] = v;
        }
        __syncthreads();

        unsigned long long acc[8][4];
#pragma unroll
        for (int i = 0; i < 8; i++)
#pragma unroll
            for (int j = 0; j < 4; j++) acc[i][j] = 0ull;

        mm_tile<CIN>(sA, sB, ty, tx, acc);

        float4 q0 = *(const float4*)(bias + tx*8);
        float4 q1 = *(const float4*)(bias + tx*8 + 4);
        float bb[8] = {q0.x,q0.y,q0.z,q0.w,q1.x,q1.y,q1.z,q1.w};
        float s8[8] = {0,0,0,0,0,0,0,0}, sq8[8] = {0,0,0,0,0,0,0,0};
#pragma unroll
        for (int i = 0; i < 8; i++) {
            size_t ro = (size_t)(m0 + ty*8 + i)*CC + tx*8;
            float2 p0 = u2f(acc[i][0]), p1 = u2f(acc[i][1]);
            float2 p2 = u2f(acc[i][2]), p3 = u2f(acc[i][3]);
            float v[8] = {p0.x+bb[0], p0.y+bb[1], p1.x+bb[2], p1.y+bb[3],
                          p2.x+bb[4], p2.y+bb[5], p3.x+bb[6], p3.y+bb[7]};
#pragma unroll
            for (int j = 0; j < 8; j++) { s8[j] += v[j]; sq8[j] = fmaf(v[j], v[j], sq8[j]); }
            *(float4*)(g_h1 + ro)     = make_float4(v[0],v[1],v[2],v[3]);
            *(float4*)(g_h1 + ro + 4) = make_float4(v[4],v[5],v[6],v[7]);
        }
        __syncthreads();
        stats_epilogue(sA, s8, sq8, ty, tx, tid, blk);
        __syncthreads();
    }
}

// ---------------- fused FPS + (kNN+GEMM1) : 136 CTAs, all wave-1, 1 CTA/SM ----------------
__global__ void __launch_bounds__(256, 1) fk_kernel(const float* __restrict__ xyz,
                                                    const float* __restrict__ points,
                                                    const float* __restrict__ b1,
                                                    float* __restrict__ outx) {
    extern __shared__ float fsm[];
    if (blockIdx.x < BB) fps_body(fsm, xyz, outx);
    else                 knng1_body(fsm, xyz, points, b1);
}

// ---------------- GEMM2 (fused stats + group max/min, NO h2 write) ----------------
__global__ void __launch_bounds__(256, 2) gemm2_kernel(const float* __restrict__ bias) {
    extern __shared__ float sm[];
    float* sA = sm;                           // 64 * SAST
    float* sB = sm + 64*SAST;                 // 64 * 128
    const int m0 = blockIdx.x * 128;
    const int tid = threadIdx.x;
    const int ty = tid >> 4, tx = tid & 15;

    unsigned long long acc[8][4];
#pragma unroll
    for (int i = 0; i < 8; i++)
#pragma unroll
        for (int j = 0; j < 4; j++) acc[i][j] = 0ull;

    for (int kc = 0; kc < CC; kc += 64) {
        __syncthreads();
        for (int idx = tid; idx < 128*64; idx += 256) {
            int r = idx >> 6, c = idx & 63;
            int ch = kc + c;
            float x = g_h1[(size_t)(m0 + r)*CC + ch];
            sA[c*SAST + r] = fmaxf(fmaf(x, g_scale[0][ch], g_shift[0][ch]), 0.0f);
        }
        for (int idx = tid; idx < 64*CC; idx += 256) sB[idx] = g_W2T[kc*CC + idx];
        __syncthreads();

        mm_tile<64>(sA, sB, ty, tx, acc);
    }
    float4 q0 = *(const float4*)(bias + tx*8);
    float4 q1 = *(const float4*)(bias + tx*8 + 4);
    float bb[8] = {q0.x,q0.y,q0.z,q0.w,q1.x,q1.y,q1.z,q1.w};
    float s8[8] = {0,0,0,0,0,0,0,0}, sq8[8] = {0,0,0,0,0,0,0,0};
    float mx8[8], mn8[8];
#pragma unroll
    for (int j = 0; j < 8; j++) { mx8[j] = -3.4e38f; mn8[j] = 3.4e38f; }
#pragma unroll
    for (int i = 0; i < 8; i++) {
        float2 p0 = u2f(acc[i][0]), p1 = u2f(acc[i][1]);
        float2 p2 = u2f(acc[i][2]), p3 = u2f(acc[i][3]);
        float v[8] = {p0.x+bb[0], p0.y+bb[1], p1.x+bb[2], p1.y+bb[3],
                      p2.x+bb[4], p2.y+bb[5], p3.x+bb[6], p3.y+bb[7]};
#pragma unroll
        for (int j = 0; j < 8; j++) {
            s8[j] += v[j]; sq8[j] = fmaf(v[j], v[j], sq8[j]);
            mx8[j] = fmaxf(mx8[j], v[j]); mn8[j] = fminf(mn8[j], v[j]);
        }
    }
    __syncthreads();
    stats_epilogue(sA, s8, sq8, ty, tx, tid, blockIdx.x);
    __syncthreads();
#pragma unroll
    for (int j = 0; j < 8; j++) {
        sA[ty*256 + tx*8 + j]       = mx8[j];
        sA[ty*256 + 128 + tx*8 + j] = mn8[j];
    }
    __syncthreads();
    for (int t2 = tid; t2 < 1024; t2 += 256) {
        int g = t2 >> 7, ch = t2 & 127;
        float mx = fmaxf(sA[(2*g)*256 + ch],       sA[(2*g+1)*256 + ch]);
        float mn = fminf(sA[(2*g)*256 + 128 + ch], sA[(2*g+1)*256 + 128 + ch]);
        size_t o = (size_t)(blockIdx.x*8 + g)*CC + ch;
        g_mx[o] = mx; g_mn[o] = mn;
    }
}

// ---------------- BN finalize ----------------
__global__ void bnfin_kernel(int layer, const float* __restrict__ g,
                             const float* __restrict__ be) {
    __shared__ float ss[256], qq[256];
    const int ch = blockIdx.x, tid = threadIdx.x;
    float s = 0.0f, q = 0.0f;
#pragma unroll
    for (int k = 0; k < 4; k++) {
        int i = tid*4 + k;
        s += g_part[i*CC + ch];
        q += g_part[1024*CC + i*CC + ch];
    }
    ss[tid] = s; qq[tid] = q;
    __syncthreads();
    for (int off = 128; off > 0; off >>= 1) {
        if (tid < off) { ss[tid] += ss[tid+off]; qq[tid] += qq[tid+off]; }
        __syncthreads();
    }
    if (tid == 0) {
        float inv = 1.0f / (float)MT;
        float mean = ss[0] * inv;
        float var  = qq[0] * inv - mean*mean;
        float rs   = rsqrtf(var + EPSBN);
        float sc   = rs * g[ch];
        g_scale[layer][ch] = sc;
        g_shift[layer][ch] = be[ch] - mean*sc;
    }
}

// ---------------- final: relu(bn(max-or-min)) ----------------
__global__ void final_kernel(float* __restrict__ out, int off) {
    int bk = blockIdx.x;
    int ch = threadIdx.x;
    float sc = g_scale[1][ch], sh = g_shift[1][ch];
    size_t o = (size_t)bk*CC + ch;
    float v = (sc >= 0.0f) ? g_mx[o] : g_mn[o];
    out[(size_t)off + o] = fmaxf(fmaf(v, sc, sh), 0.0f);
}

// ---------------- launch ----------------
extern "C" void kernel_launch(void* const* d_in, const int* in_sizes, int n_in,
                              void* d_out, int out_size) {
    const float* xyz    = (const float*)d_in[0];
    const float* points = (const float*)d_in[1];
    const float* W1     = (const float*)d_in[2];
    const float* b1     = (const float*)d_in[3];
    const float* g1     = (const float*)d_in[4];
    const float* be1    = (const float*)d_in[5];
    const float* W2     = (const float*)d_in[6];
    const float* b2     = (const float*)d_in[7];
    const float* g2     = (const float*)d_in[8];
    const float* be2    = (const float*)d_in[9];
    float* out = (float*)d_out;

    const int has_xyz = (out_size >= BB*KP*3 + BB*KP*CC) ? 1 : 0;
    float* outx = has_xyz ? out : nullptr;
    const int poff = has_xyz ? BB*KP*3 : 0;

    // knng1 needs 4*NPT + CIN*SAST + CIN*CC floats = 135216 B; also forces 1 CTA/SM
    const int fk_smem = (4*NPT + CIN*SAST + CIN*CC)*(int)sizeof(float) + 64;
    const int g2_smem = (64*SAST + 64*CC)*(int)sizeof(float);
    cudaFuncSetAttribute(fk_kernel,   cudaFuncAttributeMaxDynamicSharedMemorySize, fk_smem);
    cudaFuncSetAttribute(gemm2_kernel,cudaFuncAttributeMaxDynamicSharedMemorySize, g2_smem);

    wt1_kernel<<<1, 256>>>(W1);          // resets g_prog, transposes W1
    wt2_kernel<<<1, 256>>>(W2);
    zz_kernel<<<64, 256>>>();            // filler so ncu captures fk
    fk_kernel<<<BB + 128, 256, fk_smem>>>(xyz, points, b1, outx);
    bnfin_kernel<<<CC, 256>>>(0, g1, be1);
    gemm2_kernel<<<MT/128, 256, g2_smem>>>(b2);
    bnfin_kernel<<<CC, 256>>>(1, g2, be2);
    final_kernel<<<BB*KP, 128>>>(out, poff);
}

// round 16
// speedup vs baseline: 2.2034x; 1.0002x over previous
#include <cuda_runtime.h>

#define BB   8
#define NPT  4096
#define DD   64
#define KP   1024
#define NNB  16
#define CC   128
#define CIN  67            // D + 3
#define MT   (BB*KP*NNB)   // 131072 rows
#define EPSBN 1e-5f

// ---------------- scratch ----------------
__device__ float g_h1[(size_t)MT*CC];
__device__ float g_nxyz[BB*KP*3];
__device__ float g_W1T[CIN*CC];
__device__ float g_W2T[CC*CC];
__device__ float g_part[2*1024*CC];
__device__ float g_scale[2][CC];
__device__ float g_shift[2][CC];
__device__ float g_mx[(size_t)BB*KP*CC];
__device__ float g_mn[(size_t)BB*KP*CC];
__device__ unsigned g_prog[BB];            // FPS progress per batch

// ---------------- helpers ----------------
__device__ __forceinline__ unsigned redux_max_u32(unsigned v) {
    unsigned r; asm("redux.sync.max.u32 %0,%1,0xffffffff;" : "=r"(r) : "r"(v)); return r;
}
__device__ __forceinline__ unsigned redux_min_u32(unsigned v) {
    unsigned r; asm("redux.sync.min.u32 %0,%1,0xffffffff;" : "=r"(r) : "r"(v)); return r;
}
__device__ __forceinline__ void fma2(unsigned long long& d, unsigned long long a, unsigned long long b) {
    asm("fma.rn.f32x2 %0,%1,%2,%0;" : "+l"(d) : "l"(a), "l"(b));
}
__device__ __forceinline__ unsigned long long mul2(unsigned long long a, unsigned long long b) {
    unsigned long long r; asm("mul.rn.f32x2 %0,%1,%2;" : "=l"(r) : "l"(a), "l"(b)); return r;
}
__device__ __forceinline__ unsigned long long add2(unsigned long long a, unsigned long long b) {
    unsigned long long r; asm("add.rn.f32x2 %0,%1,%2;" : "=l"(r) : "l"(a), "l"(b)); return r;
}
__device__ __forceinline__ unsigned long long pk2(float lo, float hi) {
    unsigned long long r; asm("mov.b64 %0,{%1,%2};" : "=l"(r) : "f"(lo), "f"(hi)); return r;
}
__device__ __forceinline__ float2 u2f(unsigned long long v) {
    float2 f; asm("mov.b64 {%0,%1},%2;" : "=f"(f.x), "=f"(f.y) : "l"(v)); return f;
}

// ---------------- merged pre-kernel ----------------
__global__ void pre_kernel(const float* __restrict__ W1, const float* __restrict__ W2) {
    if (threadIdx.x < BB) g_prog[threadIdx.x] = 0u;
    for (int idx = threadIdx.x; idx < CC*CIN; idx += blockDim.x) {
        int o = idx / CIN, c = idx - o*CIN;
        g_W1T[c*CC + o] = W1[idx];
    }
    for (int idx = threadIdx.x; idx < CC*CC; idx += blockDim.x) {
        int o = idx >> 7, c = idx & 127;
        g_W2T[c*CC + o] = W2[idx];
    }
}

#define SAST 132   // scalar A tile stride (floats)

// software-pipelined fragment MM
template<int KK>
__device__ __forceinline__ void mm_tile(const float* __restrict__ sA, const float* __restrict__ sB,
                                        int ty, int tx, unsigned long long acc[8][4]) {
    const float* pa = sA + ty*8;
    const float* pb = sB + tx*8;
    float4 ca0 = *(const float4*)pa;
    float4 ca1 = *(const float4*)(pa + 4);
    ulonglong2 cb01 = *(const ulonglong2*)pb;
    ulonglong2 cb23 = *(const ulonglong2*)(pb + 4);
#pragma unroll 2
    for (int k = 0; k < KK; k++) {
        float4 na0, na1; ulonglong2 nb01, nb23;
        if (k + 1 < KK) {
            const float* qa = sA + (k+1)*SAST + ty*8;
            const float* qb = sB + (k+1)*CC + tx*8;
            na0  = *(const float4*)qa;
            na1  = *(const float4*)(qa + 4);
            nb01 = *(const ulonglong2*)qb;
            nb23 = *(const ulonglong2*)(qb + 4);
        }
        unsigned long long av[8] = {pk2(ca0.x,ca0.x), pk2(ca0.y,ca0.y), pk2(ca0.z,ca0.z), pk2(ca0.w,ca0.w),
                                    pk2(ca1.x,ca1.x), pk2(ca1.y,ca1.y), pk2(ca1.z,ca1.z), pk2(ca1.w,ca1.w)};
        unsigned long long bv[4] = {cb01.x, cb01.y, cb23.x, cb23.y};
#pragma unroll
        for (int i = 0; i < 8; i++)
#pragma unroll
            for (int j = 0; j < 4; j++) fma2(acc[i][j], av[i], bv[j]);
        ca0 = na0; ca1 = na1; cb01 = nb01; cb23 = nb23;
    }
}

// stats epilogue: per-block column sum/sumsq -> g_part (red: >=16*256 floats)
__device__ __forceinline__ void stats_epilogue(float* red, const float s8[8], const float q8[8],
                                               int ty, int tx, int tid, int blk) {
#pragma unroll
    for (int j = 0; j < 8; j++) {
        red[ty*256 + tx*8 + j]       = s8[j];
        red[ty*256 + 128 + tx*8 + j] = q8[j];
    }
    __syncthreads();
    if (tid < 128) {
        float s = 0.0f, q = 0.0f;
#pragma unroll
        for (int y = 0; y < 16; y++) {
            s += red[y*256 + tid];
            q += red[y*256 + 128 + tid];
        }
        g_part[blk*CC + tid]           = s;
        g_part[1024*CC + blk*CC + tid] = q;
    }
}

// ---------------- FPS body (blocks 0..7) ----------------
__device__ __forceinline__ void fps_body(float* fsm, const float* __restrict__ xyz,
                                         float* __restrict__ outx) {
    float4* sp = (float4*)fsm;
    unsigned* vslot = (unsigned*)(sp + NPT);
    unsigned* islot = vslot + 16;

    const int b    = blockIdx.x;
    const int st   = threadIdx.x;
    const int lane = st & 31, warp = st >> 5;
    const float* base = xyz + (size_t)b*NPT*3;

    float c[48];
    {
        const float4* s4 = (const float4*)(base + st*48);
#pragma unroll
        for (int q = 0; q < 12; q++) {
            float4 v = s4[q];
            c[4*q+0] = v.x; c[4*q+1] = v.y; c[4*q+2] = v.z; c[4*q+3] = v.w;
        }
    }
    unsigned long long pxp[8], pyp[8], pzp[8];
    float dist[16];
#pragma unroll
    for (int q = 0; q < 8; q++) {
        pxp[q] = pk2(c[6*q+0], c[6*q+3]);
        pyp[q] = pk2(c[6*q+1], c[6*q+4]);
        pzp[q] = pk2(c[6*q+2], c[6*q+5]);
        dist[2*q] = 1e10f; dist[2*q+1] = 1e10f;
    }
#pragma unroll
    for (int i = 0; i < 16; i++)
        sp[st*16 + i] = make_float4(c[3*i+0], c[3*i+1], c[3*i+2], 0.0f);
    __syncthreads();

    int far = 0;
    for (int t = 0; t < KP; t++) {
        float4 ctr = sp[far];
        if (st == 0) {
            int o = (b*KP + t)*3;
            g_nxyz[o+0] = ctr.x; g_nxyz[o+1] = ctr.y; g_nxyz[o+2] = ctr.z;
            if (outx) { outx[o+0] = ctr.x; outx[o+1] = ctr.y; outx[o+2] = ctr.z; }
            if ((t & 7) == 7) {
                __threadfence();
                *((volatile unsigned*)&g_prog[b]) = (unsigned)(t + 1);
            }
        }
        unsigned long long ncx = pk2(-ctr.x, -ctr.x), ncy = pk2(-ctr.y, -ctr.y), ncz = pk2(-ctr.z, -ctr.z);
#pragma unroll
        for (int q = 0; q < 8; q++) {
            unsigned long long dx = add2(pxp[q], ncx);
            unsigned long long dy = add2(pyp[q], ncy);
            unsigned long long dz = add2(pzp[q], ncz);
            unsigned long long dd = mul2(dx, dx);
            fma2(dd, dy, dy);
            fma2(dd, dz, dz);
            float2 e = u2f(dd);
            dist[2*q]   = fminf(dist[2*q],   e.x);
            dist[2*q+1] = fminf(dist[2*q+1], e.y);
        }
        float h[8];
#pragma unroll
        for (int i = 0; i < 8; i++) h[i] = fmaxf(dist[2*i], dist[2*i+1]);
        float h0 = fmaxf(fmaxf(h[0], h[1]), fmaxf(h[2], h[3]));
        float h1 = fmaxf(fmaxf(h[4], h[5]), fmaxf(h[6], h[7]));
        float tm = fmaxf(h0, h1);
        unsigned mb = redux_max_u32(__float_as_uint(tm));   // exact: dists >= 0
        float m = __uint_as_float(mb);
        int li = 15;
#pragma unroll
        for (int i = 14; i >= 0; i--) li = (dist[i] == m) ? i : li;
        unsigned widx = redux_min_u32((__float_as_uint(tm) == mb)
                                      ? (unsigned)(st*16 + li) : 0xFFFFFFFFu);
        const int par = (t & 1) * 8;
        if (lane == 0) { vslot[par + warp] = mb; islot[par + warp] = widx; }
        __syncthreads();
        unsigned v  = vslot[par + (lane & 7)];
        unsigned iv = islot[par + (lane & 7)];
        unsigned m2 = redux_max_u32(v);
        far = (int)redux_min_u32((v == m2) ? iv : 0xFFFFFFFFu);
    }
    if (st == 0) {
        __threadfence();
        *((volatile unsigned*)&g_prog[b]) = (unsigned)KP;
    }
}

// ---------------- kNN + GEMM1 fused body (blocks 8..135) ----------------
__device__ __forceinline__ void knng1_body(float* fsm, const float* __restrict__ xyz,
                                           const float* __restrict__ points,
                                           const float* __restrict__ bias) {
    float* spx = fsm;
    float* spy = fsm + NPT;
    float* spz = fsm + 2*NPT;
    float* sn  = fsm + 3*NPT;
    float* sA  = fsm + 4*NPT;             // CIN*SAST
    float* sB  = sA + CIN*SAST;           // CIN*CC
    __shared__ int   s_nid[128];
    __shared__ float s_ctr[24];

    const int cb = blockIdx.x - BB;        // 0..127
    const int b  = cb >> 4;                // batch 0..7
    const int g0 = cb & 15;                // stride phase
    const int tid = threadIdx.x;
    const float* base = xyz + (size_t)b*NPT*3;

    for (int j = tid; j < NPT; j += 256) {
        float x = base[j*3+0], y = base[j*3+1], z = base[j*3+2];
        spx[j] = x; spy[j] = y; spz[j] = z;
        sn[j]  = x*x + y*y + z*z;
    }
    for (int idx = tid; idx < CIN*CC; idx += 256) sB[idx] = g_W1T[idx];
    __syncthreads();

    const int w = tid >> 5, l = tid & 31;
    const int ty = tid >> 4, tx = tid & 15;

    for (int jj = 0; jj < 8; jj++) {
        const int g   = jj*16 + g0;
        const int blk = b*128 + g;
        const int m0  = blk * 128;

        if (tid == 0) {
            unsigned need = (unsigned)(g*8 + 8);
            while (*((volatile unsigned*)&g_prog[b]) < need) {}
            __threadfence();
        }
        __syncthreads();

        // ---- kNN: warp w handles center (blk*8 + w) ----
        {
            int cid = blk*8 + w;
            float cx = g_nxyz[cid*3+0], cy = g_nxyz[cid*3+1], cz = g_nxyz[cid*3+2];
            float cn = cx*cx + cy*cy + cz*cz;

            float lv = 3.4e38f; int li = 1 << 30;
            float tau = 3.4e38f; int ti = 1 << 30;

            for (int k = 0; k < 128; k++) {
                int j = k*32 + l;
                float dot = cx*spx[j] + cy*spy[j] + cz*spz[j];
                float sq  = cn + sn[j] - 2.0f*dot;
                unsigned mask = __ballot_sync(0xffffffffu, (sq < tau) || (sq == tau && j < ti));
                while (mask) {
                    int src = __ffs(mask) - 1;
                    mask &= mask - 1;
                    float cv = __shfl_sync(0xffffffffu, sq, src);
                    int   cj = k*32 + src;
                    if (cv < tau || (cv == tau && cj < ti)) {
                        bool less = (l < 16) && ((lv < cv) || (lv == cv && li < cj));
                        unsigned lm = __ballot_sync(0xffffffffu, less);
                        int pos = __popc(lm);
                        float pv = __shfl_up_sync(0xffffffffu, lv, 1);
                        int   pi = __shfl_up_sync(0xffffffffu, li, 1);
                        if (l < 16) {
                            if (l == pos)     { lv = cv; li = cj; }
                            else if (l > pos) { lv = pv; li = pi; }
                        }
                        tau = __shfl_sync(0xffffffffu, lv, 15);
                        ti  = __shfl_sync(0xffffffffu, li, 15);
                    }
                }
            }
            if (l < 16) s_nid[w*16 + l] = li;
        }
        if (tid < 24) s_ctr[tid] = g_nxyz[blk*24 + tid];
        __syncthreads();

        // ---- GEMM1 for this group's 128 rows ----
        for (int idx = tid; idx < 128*CIN; idx += 256) {
            int r = idx / CIN, c = idx - r*CIN;
            int nid = s_nid[r];
            float v;
            if (c < 3) v = xyz[((size_t)b*NPT + nid)*3 + c] - s_ctr[(r>>4)*3 + c];
            else       v = points[((size_t)b*NPT + nid)*DD + (c-3)];
            sA[c*SAST + r] = v;
        }
        __syncthreads();

        unsigned long long acc[8][4];
#pragma unroll
        for (int i = 0; i < 8; i++)
#pragma unroll
            for (int j = 0; j < 4; j++) acc[i][j] = 0ull;

        mm_tile<CIN>(sA, sB, ty, tx, acc);

        float4 q0 = *(const float4*)(bias + tx*8);
        float4 q1 = *(const float4*)(bias + tx*8 + 4);
        float bb[8] = {q0.x,q0.y,q0.z,q0.w,q1.x,q1.y,q1.z,q1.w};
        float s8[8] = {0,0,0,0,0,0,0,0}, sq8[8] = {0,0,0,0,0,0,0,0};
#pragma unroll
        for (int i = 0; i < 8; i++) {
            size_t ro = (size_t)(m0 + ty*8 + i)*CC + tx*8;
            float2 p0 = u2f(acc[i][0]), p1 = u2f(acc[i][1]);
            float2 p2 = u2f(acc[i][2]), p3 = u2f(acc[i][3]);
            float v[8] = {p0.x+bb[0], p0.y+bb[1], p1.x+bb[2], p1.y+bb[3],
                          p2.x+bb[4], p2.y+bb[5], p3.x+bb[6], p3.y+bb[7]};
#pragma unroll
            for (int j = 0; j < 8; j++) { s8[j] += v[j]; sq8[j] = fmaf(v[j], v[j], sq8[j]); }
            *(float4*)(g_h1 + ro)     = make_float4(v[0],v[1],v[2],v[3]);
            *(float4*)(g_h1 + ro + 4) = make_float4(v[4],v[5],v[6],v[7]);
        }
        __syncthreads();
        stats_epilogue(sA, s8, sq8, ty, tx, tid, blk);
        __syncthreads();
    }
}

// ---------------- fused FPS + (kNN+GEMM1) : 136 CTAs, all wave-1, 1 CTA/SM ----------------
__global__ void __launch_bounds__(256, 1) fk_kernel(const float* __restrict__ xyz,
                                                    const float* __restrict__ points,
                                                    const float* __restrict__ b1,
                                                    float* __restrict__ outx) {
    extern __shared__ float fsm[];
    if (blockIdx.x < BB) fps_body(fsm, xyz, outx);
    else                 knng1_body(fsm, xyz, points, b1);
}

// ---------------- GEMM2 (fused stats + group max/min, NO h2 write) ----------------
__global__ void __launch_bounds__(256, 2) gemm2_kernel(const float* __restrict__ bias) {
    extern __shared__ float sm[];
    float* sA = sm;                           // 64 * SAST
    float* sB = sm + 64*SAST;                 // 64 * 128
    const int m0 = blockIdx.x * 128;
    const int tid = threadIdx.x;
    const int ty = tid >> 4, tx = tid & 15;

    unsigned long long acc[8][4];
#pragma unroll
    for (int i = 0; i < 8; i++)
#pragma unroll
        for (int j = 0; j < 4; j++) acc[i][j] = 0ull;

    for (int kc = 0; kc < CC; kc += 64) {
        __syncthreads();
        for (int idx = tid; idx < 128*64; idx += 256) {
            int r = idx >> 6, c = idx & 63;
            int ch = kc + c;
            float x = g_h1[(size_t)(m0 + r)*CC + ch];
            sA[c*SAST + r] = fmaxf(fmaf(x, g_scale[0][ch], g_shift[0][ch]), 0.0f);
        }
        for (int idx = tid; idx < 64*CC; idx += 256) sB[idx] = g_W2T[kc*CC + idx];
        __syncthreads();

        mm_tile<64>(sA, sB, ty, tx, acc);
    }
    float4 q0 = *(const float4*)(bias + tx*8);
    float4 q1 = *(const float4*)(bias + tx*8 + 4);
    float bb[8] = {q0.x,q0.y,q0.z,q0.w,q1.x,q1.y,q1.z,q1.w};
    float s8[8] = {0,0,0,0,0,0,0,0}, sq8[8] = {0,0,0,0,0,0,0,0};
    float mx8[8], mn8[8];
#pragma unroll
    for (int j = 0; j < 8; j++) { mx8[j] = -3.4e38f; mn8[j] = 3.4e38f; }
#pragma unroll
    for (int i = 0; i < 8; i++) {
        float2 p0 = u2f(acc[i][0]), p1 = u2f(acc[i][1]);
        float2 p2 = u2f(acc[i][2]), p3 = u2f(acc[i][3]);
        float v[8] = {p0.x+bb[0], p0.y+bb[1], p1.x+bb[2], p1.y+bb[3],
                      p2.x+bb[4], p2.y+bb[5], p3.x+bb[6], p3.y+bb[7]};
#pragma unroll
        for (int j = 0; j < 8; j++) {
            s8[j] += v[j]; sq8[j] = fmaf(v[j], v[j], sq8[j]);
            mx8[j] = fmaxf(mx8[j], v[j]); mn8[j] = fminf(mn8[j], v[j]);
        }
    }
    __syncthreads();
    stats_epilogue(sA, s8, sq8, ty, tx, tid, blockIdx.x);
    __syncthreads();
#pragma unroll
    for (int j = 0; j < 8; j++) {
        sA[ty*256 + tx*8 + j]       = mx8[j];
        sA[ty*256 + 128 + tx*8 + j] = mn8[j];
    }
    __syncthreads();
    for (int t2 = tid; t2 < 1024; t2 += 256) {
        int g = t2 >> 7, ch = t2 & 127;
        float mx = fmaxf(sA[(2*g)*256 + ch],       sA[(2*g+1)*256 + ch]);
        float mn = fminf(sA[(2*g)*256 + 128 + ch], sA[(2*g+1)*256 + 128 + ch]);
        size_t o = (size_t)(blockIdx.x*8 + g)*CC + ch;
        g_mx[o] = mx; g_mn[o] = mn;
    }
}

// ---------------- BN finalize ----------------
__global__ void bnfin_kernel(int layer, const float* __restrict__ g,
                             const float* __restrict__ be) {
    __shared__ float ss[256], qq[256];
    const int ch = blockIdx.x, tid = threadIdx.x;
    float s = 0.0f, q = 0.0f;
#pragma unroll
    for (int k = 0; k < 4; k++) {
        int i = tid*4 + k;
        s += g_part[i*CC + ch];
        q += g_part[1024*CC + i*CC + ch];
    }
    ss[tid] = s; qq[tid] = q;
    __syncthreads();
    for (int off = 128; off > 0; off >>= 1) {
        if (tid < off) { ss[tid] += ss[tid+off]; qq[tid] += qq[tid+off]; }
        __syncthreads();
    }
    if (tid == 0) {
        float inv = 1.0f / (float)MT;
        float mean = ss[0] * inv;
        float var  = qq[0] * inv - mean*mean;
        float rs   = rsqrtf(var + EPSBN);
        float sc   = rs * g[ch];
        g_scale[layer][ch] = sc;
        g_shift[layer][ch] = be[ch] - mean*sc;
    }
}

// ---------------- final: relu(bn(max-or-min)) ----------------
__global__ void final_kernel(float* __restrict__ out, int off) {
    int bk = blockIdx.x;
    int ch = threadIdx.x;
    float sc = g_scale[1][ch], sh = g_shift[1][ch];
    size_t o = (size_t)bk*CC + ch;
    float v = (sc >= 0.0f) ? g_mx[o] : g_mn[o];
    out[(size_t)off + o] = fmaxf(fmaf(v, sc, sh), 0.0f);
}

// ---------------- launch ----------------
extern "C" void kernel_launch(void* const* d_in, const int* in_sizes, int n_in,
                              void* d_out, int out_size) {
    const float* xyz    = (const float*)d_in[0];
    const float* points = (const float*)d_in[1];
    const float* W1     = (const float*)d_in[2];
    const float* b1     = (const float*)d_in[3];
    const float* g1     = (const float*)d_in[4];
    const float* be1    = (const float*)d_in[5];
    const float* W2     = (const float*)d_in[6];
    const float* b2     = (const float*)d_in[7];
    const float* g2     = (const float*)d_in[8];
    const float* be2    = (const float*)d_in[9];
    float* out = (float*)d_out;

    const int has_xyz = (out_size >= BB*KP*3 + BB*KP*CC) ? 1 : 0;
    float* outx = has_xyz ? out : nullptr;
    const int poff = has_xyz ? BB*KP*3 : 0;

    const int fk_smem = (4*NPT + CIN*SAST + CIN*CC)*(int)sizeof(float) + 64;
    const int g2_smem = (64*SAST + 64*CC)*(int)sizeof(float);
    cudaFuncSetAttribute(fk_kernel,   cudaFuncAttributeMaxDynamicSharedMemorySize, fk_smem);
    cudaFuncSetAttribute(gemm2_kernel,cudaFuncAttributeMaxDynamicSharedMemorySize, g2_smem);

    pre_kernel<<<1, 256>>>(W1, W2);      // resets g_prog, transposes W1/W2
    fk_kernel<<<BB + 128, 256, fk_smem>>>(xyz, points, b1, outx);
    bnfin_kernel<<<CC, 256>>>(0, g1, be1);
    gemm2_kernel<<<MT/128, 256, g2_smem>>>(b2);   // ncu slot (global 5 = local 3)
    bnfin_kernel<<<CC, 256>>>(1, g2, be2);
    final_kernel<<<BB*KP, 128>>>(out, poff);
}